// round 12
// baseline (speedup 1.0000x reference)
#include <cuda_runtime.h>
#include <cuda_bf16.h>
#include <mma.h>
#include <cstdint>

using namespace nvcuda;

// ---------------------------------------------------------------------------
// CMAFM block as a pipeline of batched WMMA bf16 split-2 GEMM kernels
// (3 terms: Whi.Xhi + Whi.Xlo + Wlo.Xhi, fp32 accum, ~5e-6 rel) + one fused
// dual-direction window-attention kernel (SIMT fp32, validated).
// gemm_k: 2 CTAs/SM (104.4KB smem), CTA = 512 px, W staged per 64-k half,
// D epilogue buffer aliases the X-tile region.
// ---------------------------------------------------------------------------

#define TB 256
using u64 = unsigned long long;

constexpr int CC = 128, HH = 256, WWI = 256, XP = 132;
constexpr int BUF = 64 * XP;
constexpr size_t NTOT = 4ull * 128 * 256 * 256;
constexpr int IMG = 65536, CSTRIDE = IMG, BSTRIDE = 128 * IMG;

__device__ __align__(16) float g_scr[6ull * 33554432];
__device__ __align__(16) __nv_bfloat16 g_w2[458752];
enum { OW_QO = 0,      OW_KO = 32768,  OW_VO = 65536,  OW_QS = 98304,
       OW_KS = 131072, OW_VS = 163840, OW_PO = 196608, OW_PS = 229376,
       OW_GO = 262144, OW_GS = 327680, OW_FW = 393216 };

enum { EPI_BIAS = 0, EPI_GATE = 1, EPI_FUSE = 2 };

// smem layout (bytes)
constexpr int WKP   = 72;                 // W pitch (bf16 elems)
constexpr int WLOFF = 128 * WKP;          // 9216 elems: lo plane offset
constexpr int XOFF  = 36864;              // X tiles / D buffer base
constexpr int XPI   = 136;                // X pitch (bf16 elems)
constexpr int XLOFF = 64 * XPI;           // 8704 elems
constexpr int DP    = 132;                // D pitch (fp32)
constexpr int SMEM_G = XOFF + 128 * DP * 4;   // 104448
constexpr int SMEM_A = 3 * BUF * 4;           // 101376

struct GP {
    const float *x0, *x1;
    int wOff;
    const float *bias;
    float *dst;
    float *sgm;
    const float *gma, *bta, *mu, *var;
};
struct AP { float *q0, *k0, *v0, *q1, *k1, *v1; };
struct PPP { const float* w[11]; };

// ---- helpers --------------------------------------------------------------
__device__ __forceinline__ void f2fma(u64& d, u64 a, u64 b) {
    asm("fma.rn.f32x2 %0, %1, %2, %0;" : "+l"(d) : "l"(a), "l"(b));
}
__device__ __forceinline__ u64 f2mul(u64 a, u64 b) {
    u64 d; asm("mul.rn.f32x2 %0, %1, %2;" : "=l"(d) : "l"(a), "l"(b)); return d;
}
__device__ __forceinline__ u64 f2add(u64 a, u64 b) {
    u64 d; asm("add.rn.f32x2 %0, %1, %2;" : "=l"(d) : "l"(a), "l"(b)); return d;
}
__device__ __forceinline__ u64 dup2(float v) {
    u64 d; asm("mov.b64 %0, {%1, %1};" : "=l"(d) : "f"(v)); return d;
}
__device__ __forceinline__ float f2sum(u64 a) {
    float lo, hi; asm("mov.b64 {%0, %1}, %2;" : "=f"(lo), "=f"(hi) : "l"(a));
    return lo + hi;
}
__device__ __forceinline__ void cp16(uint32_t s, const void* g) {
    asm volatile("cp.async.cg.shared.global [%0], [%1], 16;" :: "r"(s), "l"(g));
}
__device__ __forceinline__ float sigmoidf_(float x) {
    return 1.f / (1.f + __expf(-x));
}

// ---------------------------------------------------------------------------
// Fused preproc: split all 11 weight matrices into bf16 hi/lo. grid = 896.
// ---------------------------------------------------------------------------
__global__ void preproc_all(PPP pp) {
    const int bidx = blockIdx.x;
    int n, off, i;
    const float* W;
    if (bidx < 512) {
        const int m = bidx >> 6;
        n = 16384; off = m * 32768;
        i = ((bidx & 63) << 8) + threadIdx.x;
        W = pp.w[m];
    } else {
        const int bb = bidx - 512, m = bb >> 7;
        n = 32768; off = 262144 + m * 65536;
        i = ((bb & 127) << 8) + threadIdx.x;
        W = pp.w[8 + m];
    }
    float x = W[i];
    __nv_bfloat16 h = __float2bfloat16_rn(x);
    __nv_bfloat16 l = __float2bfloat16_rn(x - __bfloat162float(h));
    g_w2[off + i] = h;
    g_w2[off + n + i] = l;
}

// ---------------------------------------------------------------------------
// Batched GEMM: D[128 ch][px] = W[128][CIN].X + epilogue. grid = 512 CTAs,
// 512 px each (4 subtiles x 128 px). K in 64-wide halves; per (sub, half):
// cp.async W-half (hi+lo, pre-split), convert X-half to bf16 hi/lo, wmma.
// ---------------------------------------------------------------------------
extern __shared__ char smem_g[];

template <int CIN, int EPI>
__global__ void __launch_bounds__(TB, 2) gemm_k(GP p) {
    const int tid = threadIdx.x;
    const int w = tid >> 5;
    const int px0 = blockIdx.x << 9;
    const int b = px0 >> 16;
    const int hw0 = px0 & (IMG - 1);
    const int nh = CIN >> 6;

    uint32_t sbase;
    asm("{ .reg .u64 t; cvta.to.shared.u64 t, %1; cvt.u32.u64 %0, t; }"
        : "=r"(sbase) : "l"(smem_g));
    __nv_bfloat16* WH = (__nv_bfloat16*)smem_g;
    __nv_bfloat16* WL = WH + WLOFF;
    __nv_bfloat16* XH = (__nv_bfloat16*)(smem_g + XOFF);
    __nv_bfloat16* XL = XH + XLOFF;
    float* Dsm = (float*)(smem_g + XOFF);           // aliases X tiles

    const int c = tid >> 1, q = tid & 1;
    const float bias_c = __ldg(p.bias + c);
    float inv_c = 0.f, sh_c = 0.f;
    if (EPI == EPI_FUSE) {
        inv_c = __ldg(p.gma + c) * rsqrtf(__ldg(p.var + c) + 1e-5f);
        sh_c  = __ldg(p.bta + c) - __ldg(p.mu + c) * inv_c;
    }
    const __nv_bfloat16* gwh = g_w2 + p.wOff;
    const __nv_bfloat16* gwl = gwh + 128 * CIN;

    wmma::fragment<wmma::accumulator, 16, 16, 16, float> acc[8];

    for (int sub = 0; sub < 4; ++sub) {
        const int hw = hw0 + sub * 128;
#pragma unroll
        for (int nt = 0; nt < 8; ++nt) wmma::fill_fragment(acc[nt], 0.0f);

        for (int h = 0; h < nh; ++h) {
            __syncthreads();   // W/X free of previous readers
            // stage W half h (hi+lo): 128 rows x 64 cols
            {
                const int koff = h * 64;
#pragma unroll
                for (int it = 0; it < 4; ++it) {
                    const int s = tid + it * TB;        // 0..1023
                    const int r = s >> 3, sg = s & 7;
                    cp16(sbase + (r * WKP + sg * 8) * 2, gwh + r * CIN + koff + sg * 8);
                    cp16(sbase + (WLOFF + r * WKP + sg * 8) * 2,
                         gwl + r * CIN + koff + sg * 8);
                }
                asm volatile("cp.async.commit_group;");
            }
            // convert X half: 64 ch x 128 px
            {
                const float* Xsrc = (CIN == 256 && h >= 2) ? p.x1 : p.x0;
                const int ch = tid >> 2, pq = (tid & 3) * 32;
                const int chg = (CIN == 256 ? (h & 1) * 64 : h * 64) + ch;
                const float* src = Xsrc + (size_t)b * BSTRIDE + chg * CSTRIDE + hw + pq;
                __nv_bfloat16* dh = XH + ch * XPI + pq;
                __nv_bfloat16* dl = XL + ch * XPI + pq;
#pragma unroll
                for (int j = 0; j < 8; ++j) {
                    float4 v = *(const float4*)(src + j * 4);
                    __nv_bfloat162 h0, h1, l0, l1;
                    h0.x = __float2bfloat16_rn(v.x); h0.y = __float2bfloat16_rn(v.y);
                    h1.x = __float2bfloat16_rn(v.z); h1.y = __float2bfloat16_rn(v.w);
                    l0.x = __float2bfloat16_rn(v.x - __bfloat162float(h0.x));
                    l0.y = __float2bfloat16_rn(v.y - __bfloat162float(h0.y));
                    l1.x = __float2bfloat16_rn(v.z - __bfloat162float(h1.x));
                    l1.y = __float2bfloat16_rn(v.w - __bfloat162float(h1.y));
                    *(__nv_bfloat162*)(dh + j * 4)     = h0;
                    *(__nv_bfloat162*)(dh + j * 4 + 2) = h1;
                    *(__nv_bfloat162*)(dl + j * 4)     = l0;
                    *(__nv_bfloat162*)(dl + j * 4 + 2) = l1;
                }
            }
            asm volatile("cp.async.wait_group 0;");
            __syncthreads();

            // wmma mainloop: warp w = M-tile w (16 out ch), 8 N-tiles
            const __nv_bfloat16* Ah = WH + w * 16 * WKP;
            const __nv_bfloat16* Al = WL + w * 16 * WKP;
#pragma unroll
            for (int kk = 0; kk < 4; ++kk) {
                wmma::fragment<wmma::matrix_a, 16, 16, 16, __nv_bfloat16,
                               wmma::row_major> ah, al;
                wmma::load_matrix_sync(ah, Ah + kk * 16, WKP);
                wmma::load_matrix_sync(al, Al + kk * 16, WKP);
#pragma unroll
                for (int nt = 0; nt < 8; ++nt) {
                    wmma::fragment<wmma::matrix_b, 16, 16, 16, __nv_bfloat16,
                                   wmma::row_major> bh, bl;
                    wmma::load_matrix_sync(bh, XH + kk * 16 * XPI + nt * 16, XPI);
                    wmma::load_matrix_sync(bl, XL + kk * 16 * XPI + nt * 16, XPI);
                    wmma::mma_sync(acc[nt], ah, bh, acc[nt]);
                    wmma::mma_sync(acc[nt], ah, bl, acc[nt]);
                    wmma::mma_sync(acc[nt], al, bh, acc[nt]);
                }
            }
        }

        // epilogue: frags -> smem D (aliases X) -> fused scalar -> global
        __syncthreads();
#pragma unroll
        for (int nt = 0; nt < 8; ++nt)
            wmma::store_matrix_sync(Dsm + w * 16 * DP + nt * 16, acc[nt], DP,
                                    wmma::mem_row_major);
        __syncthreads();
        {
            const size_t ga = (size_t)b * BSTRIDE + c * CSTRIDE + hw + q * 64;
            const float* dp = Dsm + c * DP + q * 64;
#pragma unroll
            for (int j = 0; j < 16; ++j) {
                float4 v = *(const float4*)(dp + j * 4);
                v.x += bias_c; v.y += bias_c; v.z += bias_c; v.w += bias_c;
                if (EPI == EPI_BIAS) {
                    *(float4*)(p.dst + ga + j * 4) = v;
                } else if (EPI == EPI_GATE) {
                    float4 f  = *(const float4*)(p.x0 + ga + j * 4);
                    float4 fc = *(const float4*)(p.x1 + ga + j * 4);
                    float4 s;
                    s.x = sigmoidf_(v.x); s.y = sigmoidf_(v.y);
                    s.z = sigmoidf_(v.z); s.w = sigmoidf_(v.w);
                    *(float4*)(p.sgm + ga + j * 4) = s;
                    float4 r;
                    r.x = f.x + s.x * fc.x; r.y = f.y + s.y * fc.y;
                    r.z = f.z + s.z * fc.z; r.w = f.w + s.w * fc.w;
                    *(float4*)(p.dst + ga + j * 4) = r;
                } else {
                    float4 r;
                    r.x = v.x * inv_c + sh_c; r.y = v.y * inv_c + sh_c;
                    r.z = v.z * inv_c + sh_c; r.w = v.w * inv_c + sh_c;
                    r.x *= sigmoidf_(r.x); r.y *= sigmoidf_(r.y);
                    r.z *= sigmoidf_(r.z); r.w *= sigmoidf_(r.w);
                    *(float4*)(p.dst + ga + j * 4) = r;
                }
            }
        }
    }
}

// ---------------------------------------------------------------------------
// Fused dual-direction window attention. grid = 8192: CTAs 0-4095 = o2s,
// 4096-8191 = s2o. One CTA per 8x8 window, SIMT fp32, no-max softmax.
// ---------------------------------------------------------------------------
__device__ __forceinline__ void load_window(float* dst, const float* __restrict__ src,
                                            int gbase, int tid) {
    const int c = tid >> 1, qq = tid & 1;
    const float* s = src + gbase + c * (HH * WWI) + qq * 4;
#pragma unroll
    for (int i = 0; i < 8; ++i) {
        float4 v = *(const float4*)(s + i * WWI);
        float* d = dst + (i * 8 + qq * 4) * XP + c;
        d[0] = v.x; d[XP] = v.y; d[2 * XP] = v.z; d[3 * XP] = v.w;
    }
}
__device__ __forceinline__ void store_window(float* __restrict__ g, const float* sbuf,
                                             int gbase, int tid) {
    const int c = tid >> 1, qq = tid & 1;
    float* gp = g + gbase + c * (HH * WWI) + qq * 4;
    const float* sp0 = sbuf + qq * 4 * XP + c;
#pragma unroll
    for (int i = 0; i < 8; ++i) {
        const float* sp = sp0 + i * 8 * XP;
        *(float4*)(gp + i * WWI) = make_float4(sp[0], sp[XP], sp[2 * XP], sp[3 * XP]);
    }
}

__global__ void __launch_bounds__(TB, 2) attn_k(AP a) {
    float* smem = (float*)smem_g;
    float* BQ = smem;
    float* BK = smem + BUF;
    float* BV = smem + 2 * BUF;

    const int tid = threadIdx.x;
    const int dir = blockIdx.x >> 12;
    const int widx = blockIdx.x & 4095;
    const float* Q = dir ? a.q1 : a.q0;
    const float* K = dir ? a.k1 : a.k0;
    const float* V = dir ? a.v1 : a.v0;
    float* O = dir ? a.q1 : a.q0;

    const int b = widx >> 10;
    const int wh = (widx >> 5) & 31;
    const int ww = widx & 31;
    const int gbase = b * (CC * HH * WWI) + (wh * 8) * WWI + ww * 8;

    load_window(BQ, Q, gbase, tid);
    load_window(BK, K, gbase, tid);
    load_window(BV, V, gbase, tid);
    __syncthreads();

    const int L = tid & 31, w = tid >> 5;
    const int head = w >> 1;
    const int row = (w & 1) * 32 + L;

    u64 q[16];
    {
        const ulonglong2* qp = (const ulonglong2*)(BQ + row * XP + head * 32);
        const u64 sc2 = dup2(0.17677669529663687f);  // 32^-0.5
#pragma unroll
        for (int t = 0; t < 8; ++t) {
            ulonglong2 v = qp[t];
            q[2 * t]     = f2mul(v.x, sc2);
            q[2 * t + 1] = f2mul(v.y, sc2);
        }
    }
    __syncthreads();

    const float* kbase = BK + head * 32;
    const float* vbase = BV + head * 32;
    float l = 0.f;
    u64 o[16];
#pragma unroll
    for (int t = 0; t < 16; ++t) o[t] = 0ull;

    for (int j = 0; j < 64; ++j) {
        const ulonglong2* kp = (const ulonglong2*)(kbase + j * XP);
        u64 d0 = 0ull, d1 = 0ull, d2 = 0ull, d3 = 0ull;
#pragma unroll
        for (int t = 0; t < 4; ++t) {
            ulonglong2 ka = kp[2 * t], kb = kp[2 * t + 1];
            f2fma(d0, q[4 * t],     ka.x);
            f2fma(d1, q[4 * t + 1], ka.y);
            f2fma(d2, q[4 * t + 2], kb.x);
            f2fma(d3, q[4 * t + 3], kb.y);
        }
        const float e = __expf(f2sum(f2add(f2add(d0, d1), f2add(d2, d3))));
        l += e;
        const u64 ee = dup2(e);
        const ulonglong2* vp = (const ulonglong2*)(vbase + j * XP);
#pragma unroll
        for (int t = 0; t < 8; ++t) {
            ulonglong2 v2 = vp[t];
            f2fma(o[2 * t],     ee, v2.x);
            f2fma(o[2 * t + 1], ee, v2.y);
        }
    }
    const u64 inv2 = dup2(1.f / l);
    ulonglong2* op = (ulonglong2*)(BQ + row * XP + head * 32);
#pragma unroll
    for (int t = 0; t < 8; ++t) {
        ulonglong2 r;
        r.x = f2mul(o[2 * t], inv2);
        r.y = f2mul(o[2 * t + 1], inv2);
        op[t] = r;
    }
    __syncthreads();
    store_window(O, BQ, gbase, tid);
}

// ---------------------------------------------------------------------------
extern "C" void kernel_launch(void* const* d_in, const int* in_sizes, int n_in,
                              void* d_out, int out_size) {
    (void)in_sizes; (void)n_in; (void)out_size;

    PPP pp;
    pp.w[0] = (const float*)d_in[2];  pp.w[1] = (const float*)d_in[4];
    pp.w[2] = (const float*)d_in[6];  pp.w[3] = (const float*)d_in[8];
    pp.w[4] = (const float*)d_in[10]; pp.w[5] = (const float*)d_in[12];
    pp.w[6] = (const float*)d_in[14]; pp.w[7] = (const float*)d_in[16];
    pp.w[8] = (const float*)d_in[18]; pp.w[9] = (const float*)d_in[20];
    pp.w[10] = (const float*)d_in[22];
    preproc_all<<<896, 256>>>(pp);

    float* scr = nullptr;
    cudaGetSymbolAddress((void**)&scr, g_scr);
    float* S0 = scr;
    float* S1 = scr + 1ull * NTOT;
    float* S2 = scr + 2ull * NTOT;
    float* S3 = scr + 3ull * NTOT;
    float* S4 = scr + 4ull * NTOT;
    float* S5 = scr + 5ull * NTOT;

    const float* F_opt = (const float*)d_in[0];
    const float* F_sar = (const float*)d_in[1];
    float* out = (float*)d_out;

    cudaFuncSetAttribute(gemm_k<128, EPI_BIAS>,
                         cudaFuncAttributeMaxDynamicSharedMemorySize, SMEM_G);
    cudaFuncSetAttribute(gemm_k<256, EPI_GATE>,
                         cudaFuncAttributeMaxDynamicSharedMemorySize, SMEM_G);
    cudaFuncSetAttribute(gemm_k<256, EPI_FUSE>,
                         cudaFuncAttributeMaxDynamicSharedMemorySize, SMEM_G);
    cudaFuncSetAttribute(attn_k,
                         cudaFuncAttributeMaxDynamicSharedMemorySize, SMEM_A);

    auto G = [&](const float* x0, const float* x1, int wOff, const float* bias,
                 float* dst, float* sgm, int epi,
                 const float* gma = nullptr, const float* bta = nullptr,
                 const float* mu = nullptr, const float* var = nullptr) {
        GP p{x0, x1, wOff, bias, dst, sgm, gma, bta, mu, var};
        if (epi == EPI_BIAS)      gemm_k<128, EPI_BIAS><<<512, TB, SMEM_G>>>(p);
        else if (epi == EPI_GATE) gemm_k<256, EPI_GATE><<<512, TB, SMEM_G>>>(p);
        else                      gemm_k<256, EPI_FUSE><<<512, TB, SMEM_G>>>(p);
    };

    // QKV
    G(F_opt, nullptr, OW_QO, (const float*)d_in[3],  S0, nullptr, EPI_BIAS);
    G(F_opt, nullptr, OW_KO, (const float*)d_in[5],  S1, nullptr, EPI_BIAS);
    G(F_opt, nullptr, OW_VO, (const float*)d_in[7],  S2, nullptr, EPI_BIAS);
    G(F_sar, nullptr, OW_QS, (const float*)d_in[9],  S3, nullptr, EPI_BIAS);
    G(F_sar, nullptr, OW_KS, (const float*)d_in[11], S4, nullptr, EPI_BIAS);
    G(F_sar, nullptr, OW_VS, (const float*)d_in[13], S5, nullptr, EPI_BIAS);
    // fused dual window cross attention (in-place on Q scratch)
    {
        AP a{S0, S4, S5, S3, S1, S2};
        attn_k<<<8192, TB, SMEM_A>>>(a);
    }
    // projections
    G(S0, nullptr, OW_PO, (const float*)d_in[15], S1, nullptr, EPI_BIAS);
    G(S3, nullptr, OW_PS, (const float*)d_in[17], S2, nullptr, EPI_BIAS);
    // gates (sigma + residual)
    G(F_opt, S1, OW_GO, (const float*)d_in[19], S0, out + NTOT,     EPI_GATE);
    G(F_sar, S2, OW_GS, (const float*)d_in[21], S3, out + 2 * NTOT, EPI_GATE);
    // fuse + BN + SiLU
    G(S0, S3, OW_FW, (const float*)d_in[23], out, nullptr, EPI_FUSE,
      (const float*)d_in[24], (const float*)d_in[25],
      (const float*)d_in[26], (const float*)d_in[27]);
}

// round 13
// speedup vs baseline: 1.0729x; 1.0729x over previous
#include <cuda_runtime.h>
#include <cuda_bf16.h>
#include <mma.h>
#include <cstdint>

using namespace nvcuda;
using bf16 = __nv_bfloat16;
using u64 = unsigned long long;

// ---------------------------------------------------------------------------
// CMAFM pipeline, WMMA bf16 split-2 (3 terms, fp32 accum, ~5e-6 rel).
// All GEMM inputs are pre-split bf16 hi/lo pairs in global, produced by the
// previous stage's epilogue (or an upfront conversion for F_opt/F_sar).
// gemm_k: 2 CTAs/SM, CTA=256 px (4 subtiles x 64 px), W (full K=128 chunk)
// and X staged via cp.async only — no in-kernel conversion.
// ---------------------------------------------------------------------------

#define TB 256

constexpr int CC = 128, HH = 256, WWI = 256, XP = 132;
constexpr int ABUF = 64 * XP;
constexpr size_t NTOT = 4ull * 128 * 256 * 256;    // 33,554,432
constexpr int IMG = 65536, BSTRIDE = 128 * IMG;

__device__ __align__(16) float g_scr[6ull * NTOT];         // fp32 scratch
__device__ __align__(16) bf16  g_bf[12ull * NTOT];         // 6 hi/lo pairs
__device__ __align__(16) bf16  g_w2[458752];
enum { OW_QO = 0,      OW_KO = 32768,  OW_VO = 65536,  OW_QS = 98304,
       OW_KS = 131072, OW_VS = 163840, OW_PO = 196608, OW_PS = 229376,
       OW_GO = 262144, OW_GS = 327680, OW_FW = 393216 };

enum { EPI_BIAS = 0, EPI_PROJ = 1, EPI_GATE = 2, EPI_FUSE = 3 };

// smem byte layout for gemm_k
constexpr int WPIT = 136;                    // W pitch (bf16): 272B, LDSM-clean
constexpr int XPIT = 72;                     // X pitch (bf16): 144B, LDSM-clean
constexpr int WLb  = 128 * WPIT * 2;         // 34816: W lo plane
constexpr int XOFFb = 2 * WLb;               // 69632: X region / D buffer
constexpr int XLb  = 128 * XPIT * 2;         // 18432
constexpr int DPIT = 68;                     // D fp32 pitch
constexpr int SMEM_G = XOFFb + 2 * XLb;      // 106496
constexpr int SMEM_A = 3 * ABUF * 4;         // 101376

struct GP {
    const bf16 *xa, *xb;        // pair hi bases (lo = +NTOT)
    int wOff;
    const float *bias;
    float *dst;                 // fp32 out (BIAS/PROJ/FUSE) or sigma (GATE)
    bf16 *dpair;                // pair out (PROJ/GATE)
    const float *f32a, *f32b;   // GATE: F fp32, F_proj fp32
    const float *gma, *bta, *mu, *var;
};
struct AP { const float *q0, *k0, *v0, *q1, *k1, *v1; bf16 *o0, *o1; };
struct PPP { const float* w[11]; };

// ---- helpers --------------------------------------------------------------
__device__ __forceinline__ void f2fma(u64& d, u64 a, u64 b) {
    asm("fma.rn.f32x2 %0, %1, %2, %0;" : "+l"(d) : "l"(a), "l"(b));
}
__device__ __forceinline__ u64 f2mul(u64 a, u64 b) {
    u64 d; asm("mul.rn.f32x2 %0, %1, %2;" : "=l"(d) : "l"(a), "l"(b)); return d;
}
__device__ __forceinline__ u64 f2add(u64 a, u64 b) {
    u64 d; asm("add.rn.f32x2 %0, %1, %2;" : "=l"(d) : "l"(a), "l"(b)); return d;
}
__device__ __forceinline__ u64 dup2(float v) {
    u64 d; asm("mov.b64 %0, {%1, %1};" : "=l"(d) : "f"(v)); return d;
}
__device__ __forceinline__ float f2sum(u64 a) {
    float lo, hi; asm("mov.b64 {%0, %1}, %2;" : "=f"(lo), "=f"(hi) : "l"(a));
    return lo + hi;
}
__device__ __forceinline__ void cp16(uint32_t s, const void* g) {
    asm volatile("cp.async.cg.shared.global [%0], [%1], 16;" :: "r"(s), "l"(g));
}
__device__ __forceinline__ float sigmoidf_(float x) {
    return 1.f / (1.f + __expf(-x));
}
__device__ __forceinline__ void split2(float v, bf16& h, bf16& l) {
    h = __float2bfloat16_rn(v);
    l = __float2bfloat16_rn(v - __bfloat162float(h));
}

// ---------------------------------------------------------------------------
__global__ void preproc_all(PPP pp) {
    const int bidx = blockIdx.x;
    int n, off, i;
    const float* W;
    if (bidx < 512) {
        const int m = bidx >> 6;
        n = 16384; off = m * 32768;
        i = ((bidx & 63) << 8) + threadIdx.x;
        W = pp.w[m];
    } else {
        const int bb = bidx - 512, m = bb >> 7;
        n = 32768; off = 262144 + m * 65536;
        i = ((bb & 127) << 8) + threadIdx.x;
        W = pp.w[8 + m];
    }
    float x = W[i];
    bf16 h, l; split2(x, h, l);
    g_w2[off + i] = h;
    g_w2[off + n + i] = l;
}

// Convert F_opt / F_sar to bf16 pairs. grid = 8192.
__global__ void conv_pair(const float* __restrict__ a, const float* __restrict__ b,
                          bf16* pa, bf16* pb) {
    const float* src; bf16* dh;
    if (blockIdx.x < 4096) { src = a; dh = pa; }
    else                   { src = b; dh = pb; }
    const size_t base = (size_t)(blockIdx.x & 4095) * 8192 + threadIdx.x * 4;
#pragma unroll
    for (int j = 0; j < 8; ++j) {
        const size_t off = base + j * 1024;
        float4 v = *(const float4*)(src + off);
        bf16 h0, h1, h2, h3, l0, l1, l2, l3;
        split2(v.x, h0, l0); split2(v.y, h1, l1);
        split2(v.z, h2, l2); split2(v.w, h3, l3);
        *(__nv_bfloat162*)(dh + off)     = __nv_bfloat162{h0, h1};
        *(__nv_bfloat162*)(dh + off + 2) = __nv_bfloat162{h2, h3};
        *(__nv_bfloat162*)(dh + NTOT + off)     = __nv_bfloat162{l0, l1};
        *(__nv_bfloat162*)(dh + NTOT + off + 2) = __nv_bfloat162{l2, l3};
    }
}

// ---------------------------------------------------------------------------
// GEMM: D[128 ch][px] = W[128][CIN] . X + epilogue. grid = 1024 CTAs,
// 256 px each (4 subtiles x 64 px). K in 128-chunks; W chunk resident
// (re-staged per chunk only for CIN=256), X staged per subtile. Pure
// cp.async staging of pre-split bf16 — no conversion in the mainloop.
// ---------------------------------------------------------------------------
extern __shared__ char smem_g[];

template <int CIN, int EPI>
__global__ void __launch_bounds__(TB, 2) gemm_k(GP p) {
    const int tid = threadIdx.x;
    const int w = tid >> 5;
    const int px0 = blockIdx.x << 8;
    const int b = px0 >> 16;
    const int hw0 = px0 & (IMG - 1);

    uint32_t sbase;
    asm("{ .reg .u64 t; cvta.to.shared.u64 t, %1; cvt.u32.u64 %0, t; }"
        : "=r"(sbase) : "l"(smem_g));
    bf16* WH = (bf16*)smem_g;
    bf16* WL = (bf16*)(smem_g + WLb);
    bf16* XH = (bf16*)(smem_g + XOFFb);
    bf16* XL = (bf16*)(smem_g + XOFFb + XLb);
    float* Dsm = (float*)(smem_g + XOFFb);      // aliases X (time-disjoint)

    const bf16* gwh = g_w2 + p.wOff;
    const bf16* gwl = gwh + 128 * CIN;

    const int c = tid >> 1, q = tid & 1;
    const float bias_c = __ldg(p.bias + c);
    float inv_c = 0.f, sh_c = 0.f;
    if (EPI == EPI_FUSE) {
        inv_c = __ldg(p.gma + c) * rsqrtf(__ldg(p.var + c) + 1e-5f);
        sh_c  = __ldg(p.bta + c) - __ldg(p.mu + c) * inv_c;
    }

    wmma::fragment<wmma::accumulator, 16, 16, 16, float> acc[4];

    for (int sub = 0; sub < 4; ++sub) {
        const int hw = hw0 + sub * 64;
#pragma unroll
        for (int nt = 0; nt < 4; ++nt) wmma::fill_fragment(acc[nt], 0.0f);

        for (int h = 0; h < CIN / 128; ++h) {
            __syncthreads();   // stage regions free of previous readers
            if (CIN == 256 || sub == 0) {
                const bf16* wh = gwh + h * 128;
                const bf16* wl = gwl + h * 128;
#pragma unroll
                for (int it = 0; it < 8; ++it) {
                    const int s = tid + it * TB;       // 0..2047
                    const int r = s >> 4, sg = s & 15;
                    cp16(sbase + (r * WPIT + sg * 8) * 2, wh + r * CIN + sg * 8);
                    cp16(sbase + WLb + (r * WPIT + sg * 8) * 2, wl + r * CIN + sg * 8);
                }
            }
            {
                const bf16* xh = h ? p.xb : p.xa;
                const bf16* xl = xh + NTOT;
                const size_t ga = (size_t)b * BSTRIDE + hw;
#pragma unroll
                for (int it = 0; it < 4; ++it) {
                    const int s = tid + it * TB;       // 0..1023
                    const int r = s >> 3, sg = s & 7;
                    const size_t go = ga + (size_t)r * IMG + sg * 8;
                    cp16(sbase + XOFFb + (r * XPIT + sg * 8) * 2, xh + go);
                    cp16(sbase + XOFFb + XLb + (r * XPIT + sg * 8) * 2, xl + go);
                }
            }
            asm volatile("cp.async.commit_group;");
            asm volatile("cp.async.wait_group 0;");
            __syncthreads();

            const bf16* Ah = WH + w * 16 * WPIT;
            const bf16* Al = WL + w * 16 * WPIT;
#pragma unroll
            for (int kk = 0; kk < 8; ++kk) {
                wmma::fragment<wmma::matrix_a, 16, 16, 16, bf16, wmma::row_major> ah, al;
                wmma::load_matrix_sync(ah, Ah + kk * 16, WPIT);
                wmma::load_matrix_sync(al, Al + kk * 16, WPIT);
#pragma unroll
                for (int nt = 0; nt < 4; ++nt) {
                    wmma::fragment<wmma::matrix_b, 16, 16, 16, bf16, wmma::row_major> bh, bl;
                    wmma::load_matrix_sync(bh, XH + kk * 16 * XPIT + nt * 16, XPIT);
                    wmma::load_matrix_sync(bl, XL + kk * 16 * XPIT + nt * 16, XPIT);
                    wmma::mma_sync(acc[nt], ah, bh, acc[nt]);
                    wmma::mma_sync(acc[nt], ah, bl, acc[nt]);
                    wmma::mma_sync(acc[nt], al, bh, acc[nt]);
                }
            }
        }

        __syncthreads();   // B-frag reads done before D overlays X
#pragma unroll
        for (int nt = 0; nt < 4; ++nt)
            wmma::store_matrix_sync(Dsm + w * 16 * DPIT + nt * 16, acc[nt], DPIT,
                                    wmma::mem_row_major);
        __syncthreads();
        {
            const size_t ga = (size_t)b * BSTRIDE + (size_t)c * IMG + hw + q * 32;
            const float* dp = Dsm + c * DPIT + q * 32;
#pragma unroll
            for (int j = 0; j < 8; ++j) {
                float4 v = *(const float4*)(dp + j * 4);
                v.x += bias_c; v.y += bias_c; v.z += bias_c; v.w += bias_c;
                const size_t o = ga + j * 4;
                if (EPI == EPI_BIAS) {
                    *(float4*)(p.dst + o) = v;
                } else if (EPI == EPI_PROJ) {
                    *(float4*)(p.dst + o) = v;
                    bf16 h0, h1, h2, h3, l0, l1, l2, l3;
                    split2(v.x, h0, l0); split2(v.y, h1, l1);
                    split2(v.z, h2, l2); split2(v.w, h3, l3);
                    *(__nv_bfloat162*)(p.dpair + o)     = __nv_bfloat162{h0, h1};
                    *(__nv_bfloat162*)(p.dpair + o + 2) = __nv_bfloat162{h2, h3};
                    *(__nv_bfloat162*)(p.dpair + NTOT + o)     = __nv_bfloat162{l0, l1};
                    *(__nv_bfloat162*)(p.dpair + NTOT + o + 2) = __nv_bfloat162{l2, l3};
                } else if (EPI == EPI_GATE) {
                    float4 f  = *(const float4*)(p.f32a + o);
                    float4 fc = *(const float4*)(p.f32b + o);
                    float4 s;
                    s.x = sigmoidf_(v.x); s.y = sigmoidf_(v.y);
                    s.z = sigmoidf_(v.z); s.w = sigmoidf_(v.w);
                    *(float4*)(p.dst + o) = s;
                    float4 r;
                    r.x = f.x + s.x * fc.x; r.y = f.y + s.y * fc.y;
                    r.z = f.z + s.z * fc.z; r.w = f.w + s.w * fc.w;
                    bf16 h0, h1, h2, h3, l0, l1, l2, l3;
                    split2(r.x, h0, l0); split2(r.y, h1, l1);
                    split2(r.z, h2, l2); split2(r.w, h3, l3);
                    *(__nv_bfloat162*)(p.dpair + o)     = __nv_bfloat162{h0, h1};
                    *(__nv_bfloat162*)(p.dpair + o + 2) = __nv_bfloat162{h2, h3};
                    *(__nv_bfloat162*)(p.dpair + NTOT + o)     = __nv_bfloat162{l0, l1};
                    *(__nv_bfloat162*)(p.dpair + NTOT + o + 2) = __nv_bfloat162{l2, l3};
                } else {  // FUSE: BN + SiLU
                    float4 r;
                    r.x = v.x * inv_c + sh_c; r.y = v.y * inv_c + sh_c;
                    r.z = v.z * inv_c + sh_c; r.w = v.w * inv_c + sh_c;
                    r.x *= sigmoidf_(r.x); r.y *= sigmoidf_(r.y);
                    r.z *= sigmoidf_(r.z); r.w *= sigmoidf_(r.w);
                    *(float4*)(p.dst + o) = r;
                }
            }
        }
    }
}

// ---------------------------------------------------------------------------
// Fused dual-direction window attention (SIMT fp32, validated), epilogue
// writes bf16 hi/lo pair for the following projection GEMM.
// ---------------------------------------------------------------------------
__device__ __forceinline__ void load_window(float* dst, const float* __restrict__ src,
                                            int gbase, int tid) {
    const int c = tid >> 1, qq = tid & 1;
    const float* s = src + gbase + c * IMG + qq * 4;
#pragma unroll
    for (int i = 0; i < 8; ++i) {
        float4 v = *(const float4*)(s + i * WWI);
        float* d = dst + (i * 8 + qq * 4) * XP + c;
        d[0] = v.x; d[XP] = v.y; d[2 * XP] = v.z; d[3 * XP] = v.w;
    }
}
__device__ __forceinline__ void store_window_pair(bf16* __restrict__ hi,
                                                  const float* sbuf, int gbase, int tid) {
    const int c = tid >> 1, qq = tid & 1;
    bf16* gh = hi + gbase + c * IMG + qq * 4;
    bf16* gl = gh + NTOT;
    const float* sp0 = sbuf + qq * 4 * XP + c;
#pragma unroll
    for (int i = 0; i < 8; ++i) {
        const float* sp = sp0 + i * 8 * XP;
        bf16 h0, h1, h2, h3, l0, l1, l2, l3;
        split2(sp[0], h0, l0);      split2(sp[XP], h1, l1);
        split2(sp[2 * XP], h2, l2); split2(sp[3 * XP], h3, l3);
        *(__nv_bfloat162*)(gh + i * WWI)     = __nv_bfloat162{h0, h1};
        *(__nv_bfloat162*)(gh + i * WWI + 2) = __nv_bfloat162{h2, h3};
        *(__nv_bfloat162*)(gl + i * WWI)     = __nv_bfloat162{l0, l1};
        *(__nv_bfloat162*)(gl + i * WWI + 2) = __nv_bfloat162{l2, l3};
    }
}

__global__ void __launch_bounds__(TB, 2) attn_k(AP a) {
    float* smem = (float*)smem_g;
    float* BQ = smem;
    float* BK = smem + ABUF;
    float* BV = smem + 2 * ABUF;

    const int tid = threadIdx.x;
    const int dir = blockIdx.x >> 12;
    const int widx = blockIdx.x & 4095;
    const float* Q = dir ? a.q1 : a.q0;
    const float* K = dir ? a.k1 : a.k0;
    const float* V = dir ? a.v1 : a.v0;
    bf16* O = dir ? a.o1 : a.o0;

    const int b = widx >> 10;
    const int wh = (widx >> 5) & 31;
    const int ww = widx & 31;
    const int gbase = b * BSTRIDE + (wh * 8) * WWI + ww * 8;

    load_window(BQ, Q, gbase, tid);
    load_window(BK, K, gbase, tid);
    load_window(BV, V, gbase, tid);
    __syncthreads();

    const int L = tid & 31, w = tid >> 5;
    const int head = w >> 1;
    const int row = (w & 1) * 32 + L;

    u64 q[16];
    {
        const ulonglong2* qp = (const ulonglong2*)(BQ + row * XP + head * 32);
        const u64 sc2 = dup2(0.17677669529663687f);  // 32^-0.5
#pragma unroll
        for (int t = 0; t < 8; ++t) {
            ulonglong2 v = qp[t];
            q[2 * t]     = f2mul(v.x, sc2);
            q[2 * t + 1] = f2mul(v.y, sc2);
        }
    }
    __syncthreads();

    const float* kbase = BK + head * 32;
    const float* vbase = BV + head * 32;
    float l = 0.f;
    u64 o[16];
#pragma unroll
    for (int t = 0; t < 16; ++t) o[t] = 0ull;

    for (int j = 0; j < 64; ++j) {
        const ulonglong2* kp = (const ulonglong2*)(kbase + j * XP);
        u64 d0 = 0ull, d1 = 0ull, d2 = 0ull, d3 = 0ull;
#pragma unroll
        for (int t = 0; t < 4; ++t) {
            ulonglong2 ka = kp[2 * t], kb = kp[2 * t + 1];
            f2fma(d0, q[4 * t],     ka.x);
            f2fma(d1, q[4 * t + 1], ka.y);
            f2fma(d2, q[4 * t + 2], kb.x);
            f2fma(d3, q[4 * t + 3], kb.y);
        }
        const float e = __expf(f2sum(f2add(f2add(d0, d1), f2add(d2, d3))));
        l += e;
        const u64 ee = dup2(e);
        const ulonglong2* vp = (const ulonglong2*)(vbase + j * XP);
#pragma unroll
        for (int t = 0; t < 8; ++t) {
            ulonglong2 v2 = vp[t];
            f2fma(o[2 * t],     ee, v2.x);
            f2fma(o[2 * t + 1], ee, v2.y);
        }
    }
    const u64 inv2 = dup2(1.f / l);
    ulonglong2* op = (ulonglong2*)(BQ + row * XP + head * 32);
#pragma unroll
    for (int t = 0; t < 8; ++t) {
        ulonglong2 r;
        r.x = f2mul(o[2 * t], inv2);
        r.y = f2mul(o[2 * t + 1], inv2);
        op[t] = r;
    }
    __syncthreads();
    store_window_pair(O, BQ, gbase, tid);
}

// ---------------------------------------------------------------------------
extern "C" void kernel_launch(void* const* d_in, const int* in_sizes, int n_in,
                              void* d_out, int out_size) {
    (void)in_sizes; (void)n_in; (void)out_size;

    PPP pp;
    pp.w[0] = (const float*)d_in[2];  pp.w[1] = (const float*)d_in[4];
    pp.w[2] = (const float*)d_in[6];  pp.w[3] = (const float*)d_in[8];
    pp.w[4] = (const float*)d_in[10]; pp.w[5] = (const float*)d_in[12];
    pp.w[6] = (const float*)d_in[14]; pp.w[7] = (const float*)d_in[16];
    pp.w[8] = (const float*)d_in[18]; pp.w[9] = (const float*)d_in[20];
    pp.w[10] = (const float*)d_in[22];
    preproc_all<<<896, 256>>>(pp);

    float* scr = nullptr;
    cudaGetSymbolAddress((void**)&scr, g_scr);
    bf16* bfp = nullptr;
    cudaGetSymbolAddress((void**)&bfp, g_bf);
    float* S0 = scr;
    float* S1 = scr + 1ull * NTOT;
    float* S2 = scr + 2ull * NTOT;
    float* S3 = scr + 3ull * NTOT;
    float* S4 = scr + 4ull * NTOT;
    float* S5 = scr + 5ull * NTOT;
    bf16* P0 = bfp;
    bf16* P1 = bfp + 2ull * NTOT;
    bf16* P2 = bfp + 4ull * NTOT;
    bf16* P3 = bfp + 6ull * NTOT;
    bf16* P4 = bfp + 8ull * NTOT;
    bf16* P5 = bfp + 10ull * NTOT;

    const float* F_opt = (const float*)d_in[0];
    const float* F_sar = (const float*)d_in[1];
    float* out = (float*)d_out;

    conv_pair<<<8192, 256>>>(F_opt, F_sar, P0, P1);

    cudaFuncSetAttribute(gemm_k<128, EPI_BIAS>,
                         cudaFuncAttributeMaxDynamicSharedMemorySize, SMEM_G);
    cudaFuncSetAttribute(gemm_k<128, EPI_PROJ>,
                         cudaFuncAttributeMaxDynamicSharedMemorySize, SMEM_G);
    cudaFuncSetAttribute(gemm_k<256, EPI_GATE>,
                         cudaFuncAttributeMaxDynamicSharedMemorySize, SMEM_G);
    cudaFuncSetAttribute(gemm_k<256, EPI_FUSE>,
                         cudaFuncAttributeMaxDynamicSharedMemorySize, SMEM_G);
    cudaFuncSetAttribute(attn_k,
                         cudaFuncAttributeMaxDynamicSharedMemorySize, SMEM_A);

    GP p{};
    // QKV (bias epilogue, fp32 out for attention)
    auto QKV = [&](const bf16* xa, int wOff, const float* bias, float* dst) {
        GP g{}; g.xa = xa; g.wOff = wOff; g.bias = bias; g.dst = dst;
        gemm_k<128, EPI_BIAS><<<1024, TB, SMEM_G>>>(g);
    };
    QKV(P0, OW_QO, (const float*)d_in[3],  S0);
    QKV(P0, OW_KO, (const float*)d_in[5],  S1);
    QKV(P0, OW_VO, (const float*)d_in[7],  S2);
    QKV(P1, OW_QS, (const float*)d_in[9],  S3);
    QKV(P1, OW_KS, (const float*)d_in[11], S4);
    QKV(P1, OW_VS, (const float*)d_in[13], S5);

    // fused dual window cross attention -> pairs
    {
        AP a{S0, S4, S5, S3, S1, S2, P2, P3};
        attn_k<<<8192, TB, SMEM_A>>>(a);
    }

    // projections -> fp32 + pair
    {
        GP g{}; g.xa = P2; g.wOff = OW_PO; g.bias = (const float*)d_in[15];
        g.dst = S0; g.dpair = P4;
        gemm_k<128, EPI_PROJ><<<1024, TB, SMEM_G>>>(g);
    }
    {
        GP g{}; g.xa = P3; g.wOff = OW_PS; g.bias = (const float*)d_in[17];
        g.dst = S1; g.dpair = P5;
        gemm_k<128, EPI_PROJ><<<1024, TB, SMEM_G>>>(g);
    }

    // gates: sigma fp32 out + F_new pair (reuse P2/P3)
    {
        GP g{}; g.xa = P0; g.xb = P4; g.wOff = OW_GO;
        g.bias = (const float*)d_in[19]; g.dst = out + NTOT; g.dpair = P2;
        g.f32a = F_opt; g.f32b = S0;
        gemm_k<256, EPI_GATE><<<1024, TB, SMEM_G>>>(g);
    }
    {
        GP g{}; g.xa = P1; g.xb = P5; g.wOff = OW_GS;
        g.bias = (const float*)d_in[21]; g.dst = out + 2 * NTOT; g.dpair = P3;
        g.f32a = F_sar; g.f32b = S1;
        gemm_k<256, EPI_GATE><<<1024, TB, SMEM_G>>>(g);
    }

    // fuse + BN + SiLU
    {
        GP g{}; g.xa = P2; g.xb = P3; g.wOff = OW_FW;
        g.bias = (const float*)d_in[23]; g.dst = out;
        g.gma = (const float*)d_in[24]; g.bta = (const float*)d_in[25];
        g.mu  = (const float*)d_in[26]; g.var = (const float*)d_in[27];
        gemm_k<256, EPI_FUSE><<<1024, TB, SMEM_G>>>(g);
    }
    (void)p;
}